// round 4
// baseline (speedup 1.0000x reference)
#include <cuda_runtime.h>
#include <cstdint>

// Problem constants
#define BB 2
#define TT 2048
#define CC 768
#define NH 12
#define HD 64
#define MM (BB*TT)        // 4096 rows
#define C3 (3*CC)         // 2304

typedef unsigned long long u64;

// Scratch (allocation-free rule: __device__ globals)
__device__ float g_qkv[(size_t)MM * C3];   // [M, 3C]
__device__ float g_att[(size_t)MM * CC];   // [M, C] attention output (pre-proj)

// ---------------- packed f32x2 helpers (Blackwell FFMA2) --------------------
__device__ __forceinline__ u64 dup2(float x) {
    u64 d;
    asm("mov.b64 %0, {%1, %1};" : "=l"(d) : "r"(__float_as_uint(x)));
    return d;
}
__device__ __forceinline__ void ffma2(u64& d, u64 a, u64 b) {
    asm("fma.rn.f32x2 %0, %1, %2, %0;" : "+l"(d) : "l"(a), "l"(b));
}
__device__ __forceinline__ u64 mul2(u64 a, u64 b) {
    u64 d;
    asm("mul.rn.f32x2 %0, %1, %2;" : "=l"(d) : "l"(a), "l"(b));
    return d;
}
__device__ __forceinline__ float2 unpack2(u64 d) {
    unsigned lo, hi;
    asm("mov.b64 {%0, %1}, %2;" : "=r"(lo), "=r"(hi) : "l"(d));
    return make_float2(__uint_as_float(lo), __uint_as_float(hi));
}

// ---------------------------------------------------------------------------
// SGEMM: out[M,N] = A[M,K] * W[N,K]^T  (row-major both), f32x2 micro-kernel.
// 128x128 tile, BK=8, 256 threads, 8x8 micro (as 8 rows x 4 col-pairs),
// double-buffered smem.
// ---------------------------------------------------------------------------
__global__ void __launch_bounds__(256) sgemm128(const float* __restrict__ A,
                                                const float* __restrict__ W,
                                                float* __restrict__ out,
                                                int Ndim, int Kdim)
{
    __shared__ float As[2][8][128];   // As[buf][k][m]
    __shared__ float Bs[2][8][128];   // Bs[buf][k][n]

    const int tid = threadIdx.x;
    const int m0 = blockIdx.y * 128;
    const int n0 = blockIdx.x * 128;

    const int lr = tid >> 1;            // 0..127
    const int lk = (tid & 1) << 2;      // 0 or 4
    const float* Ap = A + (size_t)(m0 + lr) * Kdim + lk;
    const float* Wp = W + (size_t)(n0 + lr) * Kdim + lk;

    const int tx = (tid & 15) << 3;     // n offset 0..120
    const int ty = (tid >> 4) << 3;     // m offset 0..120

    u64 acc2[8][4] = {};                // 8 rows x 4 col-pairs

    const int numTiles = Kdim >> 3;

    {
        float4 av = *(const float4*)Ap;
        float4 wv = *(const float4*)Wp;
        As[0][lk + 0][lr] = av.x; As[0][lk + 1][lr] = av.y;
        As[0][lk + 2][lr] = av.z; As[0][lk + 3][lr] = av.w;
        Bs[0][lk + 0][lr] = wv.x; Bs[0][lk + 1][lr] = wv.y;
        Bs[0][lk + 2][lr] = wv.z; Bs[0][lk + 3][lr] = wv.w;
    }
    __syncthreads();

    int buf = 0;
    for (int kt = 0; kt < numTiles; kt++) {
        float4 av, wv;
        const bool more = (kt + 1) < numTiles;
        if (more) {
            const int k0 = (kt + 1) << 3;
            av = *(const float4*)(Ap + k0);
            wv = *(const float4*)(Wp + k0);
        }

        #pragma unroll
        for (int k = 0; k < 8; k++) {
            float a[8];
            *(float4*)&a[0] = *(const float4*)&As[buf][k][ty];
            *(float4*)&a[4] = *(const float4*)&As[buf][k][ty + 4];
            ulonglong2 t0 = *(const ulonglong2*)&Bs[buf][k][tx];
            ulonglong2 t1 = *(const ulonglong2*)&Bs[buf][k][tx + 4];
            u64 b2[4] = {t0.x, t0.y, t1.x, t1.y};
            #pragma unroll
            for (int i = 0; i < 8; i++) {
                u64 ad = dup2(a[i]);
                #pragma unroll
                for (int j = 0; j < 4; j++) ffma2(acc2[i][j], ad, b2[j]);
            }
        }

        if (more) {
            const int nb = buf ^ 1;
            As[nb][lk + 0][lr] = av.x; As[nb][lk + 1][lr] = av.y;
            As[nb][lk + 2][lr] = av.z; As[nb][lk + 3][lr] = av.w;
            Bs[nb][lk + 0][lr] = wv.x; Bs[nb][lk + 1][lr] = wv.y;
            Bs[nb][lk + 2][lr] = wv.z; Bs[nb][lk + 3][lr] = wv.w;
            __syncthreads();
            buf = nb;
        }
    }

    #pragma unroll
    for (int i = 0; i < 8; i++) {
        float2 p0 = unpack2(acc2[i][0]);
        float2 p1 = unpack2(acc2[i][1]);
        float2 p2 = unpack2(acc2[i][2]);
        float2 p3 = unpack2(acc2[i][3]);
        float* orow = out + (size_t)(m0 + ty + i) * Ndim + n0 + tx;
        *(float4*)orow       = make_float4(p0.x, p0.y, p1.x, p1.y);
        *(float4*)(orow + 4) = make_float4(p2.x, p2.y, p3.x, p3.y);
    }
}

// ---------------------------------------------------------------------------
// Flash attention, fp32 with f32x2 FMAs.
// Grid: (T/128, H, B). Block 256. 128-query x 64-key tiles, D=64.
// Micro-tile: 4 rows x 8 cols (4 col-pairs). Softmax stats in registers,
// row reductions via warp shfl (8 lanes per row-set).
// ---------------------------------------------------------------------------
#define QTILE 128
#define SMEM_FLASH ((64*132 + 64*68 + 64*68 + 128*68) * 4)

__global__ void __launch_bounds__(256) flash_attn(const float* __restrict__ qkv,
                                                  float* __restrict__ att)
{
    extern __shared__ float sm[];
    float* Qt = sm;                    // [64][132]  Qt[d][r]
    float* Kt = Qt + 64 * 132;         // [64][68]   Kt[d][c]
    float* Vs = Kt + 64 * 68;          // [64][68]   Vs[c][d]
    float* Ps = Vs + 64 * 68;          // [128][68]  Ps[r][c]

    const int tid = threadIdx.x;
    const int tx  = tid & 7;           // col group: cols 8*tx .. 8*tx+7
    const int tyq = tid >> 3;          // row group: rows 4*tyq .. 4*tyq+3
    const int qi = blockIdx.x;
    const int h  = blockIdx.y;
    const int b  = blockIdx.z;
    const int q0 = qi * QTILE;
    const float scale = 0.125f;        // 1/sqrt(64)

    // Load Q tile transposed: Qt[d][r]
    for (int e = tid; e < QTILE * 64; e += 256) {
        int d = e & 63, r = e >> 6;
        Qt[d * 132 + r] = qkv[(size_t)(b * TT + q0 + r) * C3 + h * HD + d];
    }

    u64 acc2[4][4] = {};               // 4 rows x 4 col-pairs (8 cols)
    float m_r[4], l_r[4];
    #pragma unroll
    for (int i = 0; i < 4; i++) { m_r[i] = -1e30f; l_r[i] = 0.0f; }

    __syncthreads();

    const int ktEnd = 2 * qi + 2;      // tiles of 64 keys
    for (int kt = 0; kt < ktEnd; kt++) {
        const int kb = kt * 64;
        // Load K (transposed) and V tiles
        for (int e = tid; e < 64 * 64; e += 256) {
            int d = e & 63, c = e >> 6;
            size_t row = (size_t)(b * TT + kb + c) * C3 + h * HD;
            Kt[d * 68 + c] = qkv[row + CC + d];
            Vs[c * 68 + d] = qkv[row + 2 * CC + d];
        }
        __syncthreads();

        // ---- S = Q @ K^T (f32x2) ----
        u64 s2[4][4] = {};
        #pragma unroll 8
        for (int k = 0; k < 64; k++) {
            float4 aq = *(const float4*)&Qt[k * 132 + (tyq << 2)];
            ulonglong2 t0 = *(const ulonglong2*)&Kt[k * 68 + (tx << 3)];
            ulonglong2 t1 = *(const ulonglong2*)&Kt[k * 68 + (tx << 3) + 4];
            u64 b2[4] = {t0.x, t0.y, t1.x, t1.y};
            float a[4] = {aq.x, aq.y, aq.z, aq.w};
            #pragma unroll
            for (int i = 0; i < 4; i++) {
                u64 ad = dup2(a[i]);
                #pragma unroll
                for (int j = 0; j < 4; j++) ffma2(s2[i][j], ad, b2[j]);
            }
        }

        // ---- mask + online softmax (registers + shfl) ----
        const bool maskTile = (kt >= 2 * qi);
        #pragma unroll
        for (int i = 0; i < 4; i++) {
            const int rr = (tyq << 2) + i;
            float p[8];
            #pragma unroll
            for (int j = 0; j < 4; j++) {
                float2 v = unpack2(s2[i][j]);
                p[2 * j]     = v.x * scale;
                p[2 * j + 1] = v.y * scale;
            }
            if (maskTile) {
                const int query = q0 + rr;
                #pragma unroll
                for (int j = 0; j < 8; j++)
                    if (kb + (tx << 3) + j > query) p[j] = -1e30f;
            }
            float mx = p[0];
            #pragma unroll
            for (int j = 1; j < 8; j++) mx = fmaxf(mx, p[j]);
            mx = fmaxf(mx, __shfl_xor_sync(0xFFFFFFFFu, mx, 1));
            mx = fmaxf(mx, __shfl_xor_sync(0xFFFFFFFFu, mx, 2));
            mx = fmaxf(mx, __shfl_xor_sync(0xFFFFFFFFu, mx, 4));
            float mn = fmaxf(m_r[i], mx);
            float sum = 0.0f;
            #pragma unroll
            for (int j = 0; j < 8; j++) {
                p[j] = __expf(p[j] - mn);
                sum += p[j];
            }
            sum += __shfl_xor_sync(0xFFFFFFFFu, sum, 1);
            sum += __shfl_xor_sync(0xFFFFFFFFu, sum, 2);
            sum += __shfl_xor_sync(0xFFFFFFFFu, sum, 4);
            float cr = __expf(m_r[i] - mn);
            l_r[i] = l_r[i] * cr + sum;
            m_r[i] = mn;
            // rescale O accumulator
            u64 c2 = dup2(cr);
            #pragma unroll
            for (int j = 0; j < 4; j++) acc2[i][j] = mul2(acc2[i][j], c2);
            // store P row
            float* prow = &Ps[rr * 68 + (tx << 3)];
            *(float4*)prow       = make_float4(p[0], p[1], p[2], p[3]);
            *(float4*)(prow + 4) = make_float4(p[4], p[5], p[6], p[7]);
        }
        __syncthreads();

        // ---- O += P @ V (f32x2) ----
        #pragma unroll 4
        for (int kk = 0; kk < 64; kk += 4) {
            float4 pa[4];
            #pragma unroll
            for (int i = 0; i < 4; i++)
                pa[i] = *(const float4*)&Ps[((tyq << 2) + i) * 68 + kk];
            #pragma unroll
            for (int dk = 0; dk < 4; dk++) {
                ulonglong2 t0 = *(const ulonglong2*)&Vs[(kk + dk) * 68 + (tx << 3)];
                ulonglong2 t1 = *(const ulonglong2*)&Vs[(kk + dk) * 68 + (tx << 3) + 4];
                u64 b2[4] = {t0.x, t0.y, t1.x, t1.y};
                #pragma unroll
                for (int i = 0; i < 4; i++) {
                    float av = (dk == 0) ? pa[i].x : (dk == 1) ? pa[i].y
                             : (dk == 2) ? pa[i].z : pa[i].w;
                    u64 ad = dup2(av);
                    #pragma unroll
                    for (int j = 0; j < 4; j++) ffma2(acc2[i][j], ad, b2[j]);
                }
            }
        }
        __syncthreads();   // protect Kt/Vs/Ps before next iteration
    }

    // Normalize and write out
    #pragma unroll
    for (int i = 0; i < 4; i++) {
        float inv = 1.0f / l_r[i];
        float2 p0 = unpack2(acc2[i][0]);
        float2 p1 = unpack2(acc2[i][1]);
        float2 p2 = unpack2(acc2[i][2]);
        float2 p3 = unpack2(acc2[i][3]);
        float* orow = &att[(size_t)(b * TT + q0 + (tyq << 2) + i) * CC + h * HD + (tx << 3)];
        *(float4*)orow       = make_float4(p0.x * inv, p0.y * inv, p1.x * inv, p1.y * inv);
        *(float4*)(orow + 4) = make_float4(p2.x * inv, p2.y * inv, p3.x * inv, p3.y * inv);
    }
}

// ---------------------------------------------------------------------------
extern "C" void kernel_launch(void* const* d_in, const int* in_sizes, int n_in,
                              void* d_out, int out_size)
{
    const float* x      = (const float*)d_in[0];   // [B,T,C]
    const float* W_attn = (const float*)d_in[1];   // [3C, C]
    const float* W_proj = (const float*)d_in[2];   // [C, C]
    float* out = (float*)d_out;                    // [B,T,C]

    void* qkv_ptr = nullptr;
    void* att_ptr = nullptr;
    cudaGetSymbolAddress(&qkv_ptr, g_qkv);
    cudaGetSymbolAddress(&att_ptr, g_att);

    cudaFuncSetAttribute(flash_attn, cudaFuncAttributeMaxDynamicSharedMemorySize,
                         SMEM_FLASH);

    // 1) QKV projection: [4096,768] x [2304,768]^T -> [4096,2304]
    sgemm128<<<dim3(C3 / 128, MM / 128), 256>>>(x, W_attn, (float*)qkv_ptr, C3, CC);

    // 2) Fused causal attention -> [4096,768]
    flash_attn<<<dim3(TT / QTILE, NH, BB), 256, SMEM_FLASH>>>((const float*)qkv_ptr,
                                                              (float*)att_ptr);

    // 3) Output projection: [4096,768] x [768,768]^T -> [4096,768]
    sgemm128<<<dim3(CC / 128, MM / 128), 256>>>((const float*)att_ptr, W_proj, out,
                                                CC, CC);
}

// round 6
// speedup vs baseline: 1.5007x; 1.5007x over previous
#include <cuda_runtime.h>
#include <cuda_bf16.h>
#include <cstdint>

// Problem constants
#define BB 2
#define TT 2048
#define CC 768
#define NH 12
#define HD 64
#define MM (BB*TT)        // 4096
#define C3 (3*CC)         // 2304

typedef unsigned int u32;

// ---------------- scratch (__device__ globals; no allocation) ---------------
__device__ float g_qkv[(size_t)MM * C3];
__device__ float g_att[(size_t)MM * CC];
__device__ __nv_bfloat16 g_xhi[(size_t)MM * CC],  g_xlo[(size_t)MM * CC];
__device__ __nv_bfloat16 g_wahi[(size_t)C3 * CC], g_walo[(size_t)C3 * CC];
__device__ __nv_bfloat16 g_wphi[(size_t)CC * CC], g_wplo[(size_t)CC * CC];
__device__ __nv_bfloat16 g_ahi[(size_t)MM * CC],  g_alo[(size_t)MM * CC];

extern __shared__ char dynsm[];

__device__ __forceinline__ u32 smem_u32(const void* p) {
    u32 a;
    asm("{ .reg .u64 t; cvta.to.shared.u64 t, %1; cvt.u32.u64 %0, t; }"
        : "=r"(a) : "l"(p));
    return a;
}

// ldmatrix x4 (b16)
#define LDM_X4(r0, r1, r2, r3, addr)                                          \
    asm volatile("ldmatrix.sync.aligned.m8n8.x4.shared.b16 {%0,%1,%2,%3}, [%4];" \
        : "=r"(r0), "=r"(r1), "=r"(r2), "=r"(r3) : "r"(addr))

// m16n8k16 bf16 MMA, fp32 accumulate (D==C in-place)
#define MMA16816(d, a, b)                                                     \
    asm volatile("mma.sync.aligned.m16n8k16.row.col.f32.bf16.bf16.f32 "       \
        "{%0,%1,%2,%3}, {%4,%5,%6,%7}, {%8,%9}, {%0,%1,%2,%3};"               \
        : "+f"((d)[0]), "+f"((d)[1]), "+f"((d)[2]), "+f"((d)[3])              \
        : "r"((a)[0]), "r"((a)[1]), "r"((a)[2]), "r"((a)[3]),                 \
          "r"((b)[0]), "r"((b)[1]))

// ---------------------------------------------------------------------------
// fp32 -> (bf16_hi, bf16_lo) split, elementwise
// ---------------------------------------------------------------------------
__global__ void split_hl(const float* __restrict__ in, __nv_bfloat16* __restrict__ hi,
                         __nv_bfloat16* __restrict__ lo, int n)
{
    int i = blockIdx.x * blockDim.x + threadIdx.x;
    int stride = gridDim.x * blockDim.x;
    for (; i < n; i += stride) {
        float v = in[i];
        __nv_bfloat16 h = __float2bfloat16(v);
        hi[i] = h;
        lo[i] = __float2bfloat16(v - __bfloat162float(h));
    }
}

// ---------------------------------------------------------------------------
// Split-bf16 HMMA GEMM: out[M,N] = A[M,K] * B[N,K]^T (fp32-accurate, 3-pass).
// 128x128 CTA tile, K chunks of 64, 256 threads (8 warps, 2m x 4n grid,
// warp tile 64x32). smem pitch 72 bf16 (144B) -> ldmatrix conflict-free.
// ---------------------------------------------------------------------------
#define PITCHB 144                       // bytes per smem row (72 bf16)
#define TILE_B (128 * PITCHB)            // 18432 B per tile
#define HG_SMEM (4 * TILE_B)             // 73728 B

__global__ void __launch_bounds__(256) hgemm128(
    const __nv_bfloat16* __restrict__ Ahi, const __nv_bfloat16* __restrict__ Alo,
    const __nv_bfloat16* __restrict__ Bhi, const __nv_bfloat16* __restrict__ Blo,
    float* __restrict__ out, int Ndim, int Kdim)
{
    char* smem = dynsm;
    const u32 sb = smem_u32(smem);
    const int tid = threadIdx.x;
    const int lane = tid & 31;
    const int wid = tid >> 5;
    const int wm = (wid & 1) * 64;       // warp m offset (2 warps in m)
    const int wn = (wid >> 1) * 32;      // warp n offset (4 warps in n)
    const int m0 = blockIdx.y * 128, n0 = blockIdx.x * 128;

    const u32 SA_HI = 0, SA_LO = TILE_B, SB_HI = 2 * TILE_B, SB_LO = 3 * TILE_B;

    const __nv_bfloat16* srcs[4] = {
        Ahi + (size_t)m0 * Kdim, Alo + (size_t)m0 * Kdim,
        Bhi + (size_t)n0 * Kdim, Blo + (size_t)n0 * Kdim };
    const u32 dsts[4] = { SA_HI, SA_LO, SB_HI, SB_LO };

    // ldmatrix lane-address components (byte offsets within a tile)
    // A frag: row = wm + (lane&15) [+16*fi], col16 = kf + ((lane>>4)<<3)
    const u32 a_row_off = (u32)(wm + (lane & 15)) * PITCHB;
    const u32 a_col_off = (u32)((lane >> 4) << 3) * 2;
    // B frag pair p: n = wn + 16p + (lane&7) + ((lane>>4)<<3), k = kf + (((lane>>3)&1)<<3)
    const u32 b_row_off = (u32)(wn + (lane & 7) + ((lane >> 4) << 3)) * PITCHB;
    const u32 b_col_off = (u32)(((lane >> 3) & 1) << 3) * 2;

    float acc[4][4][4] = {};             // [fi][fj][4]

    const int nChunks = Kdim >> 6;       // 12 for K=768

    for (int kt = 0; kt < nChunks; kt++) {
        __syncthreads();                 // protect previous iteration's reads
        // Load 4 tiles: 128 rows x 64 bf16 each (uint4 = 8 bf16 per ld)
        #pragma unroll
        for (int t = 0; t < 4; t++) {
            const __nv_bfloat16* base = srcs[t] + kt * 64;
            #pragma unroll
            for (int i = 0; i < 4; i++) {
                int idx = i * 256 + tid;             // 0..1023
                int r = idx >> 3, s = idx & 7;       // row, 16B segment
                uint4 v = *(const uint4*)(base + (size_t)r * Kdim + s * 8);
                *(uint4*)(smem + dsts[t] + r * PITCHB + s * 16) = v;
            }
        }
        __syncthreads();

        #pragma unroll
        for (int kf = 0; kf < 64; kf += 16) {
            const u32 kbyte = (u32)kf * 2;
            u32 ah[4][4], bcur[4][2], aother[4][4];

            // --- load A_hi frags ---
            #pragma unroll
            for (int fi = 0; fi < 4; fi++) {
                u32 ad = sb + SA_HI + a_row_off + fi * (16 * PITCHB) + kbyte + a_col_off;
                LDM_X4(ah[fi][0], ah[fi][1], ah[fi][2], ah[fi][3], ad);
            }
            // --- load B_hi frags (2 ldmatrix -> 4 n8 frags) ---
            #pragma unroll
            for (int p = 0; p < 2; p++) {
                u32 bd = sb + SB_HI + b_row_off + p * (16 * PITCHB) + kbyte + b_col_off;
                LDM_X4(bcur[2*p][0], bcur[2*p][1], bcur[2*p+1][0], bcur[2*p+1][1], bd);
            }
            // pass 1: hi * hi
            #pragma unroll
            for (int fi = 0; fi < 4; fi++)
                #pragma unroll
                for (int fj = 0; fj < 4; fj++)
                    MMA16816(acc[fi][fj], ah[fi], bcur[fj]);

            // --- load A_lo frags; pass 2: lo * hi ---
            #pragma unroll
            for (int fi = 0; fi < 4; fi++) {
                u32 ad = sb + SA_LO + a_row_off + fi * (16 * PITCHB) + kbyte + a_col_off;
                LDM_X4(aother[fi][0], aother[fi][1], aother[fi][2], aother[fi][3], ad);
            }
            #pragma unroll
            for (int fi = 0; fi < 4; fi++)
                #pragma unroll
                for (int fj = 0; fj < 4; fj++)
                    MMA16816(acc[fi][fj], aother[fi], bcur[fj]);

            // --- load B_lo frags (overwrite bcur); pass 3: hi * lo ---
            #pragma unroll
            for (int p = 0; p < 2; p++) {
                u32 bd = sb + SB_LO + b_row_off + p * (16 * PITCHB) + kbyte + b_col_off;
                LDM_X4(bcur[2*p][0], bcur[2*p][1], bcur[2*p+1][0], bcur[2*p+1][1], bd);
            }
            #pragma unroll
            for (int fi = 0; fi < 4; fi++)
                #pragma unroll
                for (int fj = 0; fj < 4; fj++)
                    MMA16816(acc[fi][fj], ah[fi], bcur[fj]);
        }
    }

    // Epilogue: direct fragment stores (float2 per lane per half-frag)
    const int rbase = m0 + wm + (lane >> 2);
    const int cbase = n0 + wn + 2 * (lane & 3);
    #pragma unroll
    for (int fi = 0; fi < 4; fi++) {
        #pragma unroll
        for (int fj = 0; fj < 4; fj++) {
            float* o0 = out + (size_t)(rbase + 16 * fi) * Ndim + cbase + 8 * fj;
            float* o1 = out + (size_t)(rbase + 16 * fi + 8) * Ndim + cbase + 8 * fj;
            *(float2*)o0 = make_float2(acc[fi][fj][0], acc[fi][fj][1]);
            *(float2*)o1 = make_float2(acc[fi][fj][2], acc[fi][fj][3]);
        }
    }
}

// ---------------------------------------------------------------------------
// Flash attention (round-3 proven version): fp32, 64x64 tiles, D=64.
// ---------------------------------------------------------------------------
#define SMEM_FLASH ((4*64*68 + 3*64) * 4)

__global__ void __launch_bounds__(256) flash_attn(const float* __restrict__ qkv,
                                                  float* __restrict__ att)
{
    float* sm = (float*)dynsm;
    float (*Qt)[68] = (float(*)[68])(sm);
    float (*Kt)[68] = (float(*)[68])(sm + 64 * 68);
    float (*Vs)[68] = (float(*)[68])(sm + 2 * 64 * 68);
    float (*St)[68] = (float(*)[68])(sm + 3 * 64 * 68);
    float* m_s    = sm + 4 * 64 * 68;
    float* l_s    = m_s + 64;
    float* corr_s = l_s + 64;

    const int tid = threadIdx.x;
    const int tx = tid & 15;
    const int ty = tid >> 4;
    const int qi = blockIdx.x;
    const int h  = blockIdx.y;
    const int b  = blockIdx.z;
    const int q0 = qi * 64;
    const float scale = 0.125f;

    for (int e = tid; e < 64 * 64; e += 256) {
        int d = e & 63, r = e >> 6;
        Qt[d][r] = qkv[(size_t)(b * TT + q0 + r) * C3 + h * HD + d];
    }
    if (tid < 64) { m_s[tid] = -1e30f; l_s[tid] = 0.0f; }

    float acc[4][4] = {};
    __syncthreads();

    for (int kt = 0; kt <= qi; kt++) {
        const int kb = kt * 64;
        for (int e = tid; e < 64 * 64; e += 256) {
            int d = e & 63, c = e >> 6;
            size_t row = (size_t)(b * TT + kb + c) * C3 + h * HD;
            Kt[d][c] = qkv[row + CC + d];
            Vs[c][d] = qkv[row + 2 * CC + d];
        }
        __syncthreads();

        float s[4][4] = {};
        #pragma unroll 16
        for (int k = 0; k < 64; k++) {
            float4 a = *(const float4*)&Qt[k][ty << 2];
            float4 bb = *(const float4*)&Kt[k][tx << 2];
            float ar[4] = {a.x, a.y, a.z, a.w};
            float br[4] = {bb.x, bb.y, bb.z, bb.w};
            #pragma unroll
            for (int i = 0; i < 4; i++)
                #pragma unroll
                for (int j = 0; j < 4; j++)
                    s[i][j] = fmaf(ar[i], br[j], s[i][j]);
        }

        const bool diag = (kt == qi);
        #pragma unroll
        for (int i = 0; i < 4; i++) {
            int rr = (ty << 2) + i;
            #pragma unroll
            for (int j = 0; j < 4; j++) {
                int cc = (tx << 2) + j;
                float v = s[i][j] * scale;
                if (diag && cc > rr) v = -1e30f;
                St[cc][rr] = v;
            }
        }
        __syncthreads();

        {
            const int r    = tid >> 2;
            const int part = tid & 3;
            const int c0   = part << 4;
            float mx = -1e30f;
            #pragma unroll
            for (int c = c0; c < c0 + 16; c++) mx = fmaxf(mx, St[c][r]);
            mx = fmaxf(mx, __shfl_xor_sync(0xFFFFFFFFu, mx, 1));
            mx = fmaxf(mx, __shfl_xor_sync(0xFFFFFFFFu, mx, 2));
            float mo = m_s[r];
            float mn = fmaxf(mo, mx);
            float sum = 0.0f;
            #pragma unroll
            for (int c = c0; c < c0 + 16; c++) {
                float p = __expf(St[c][r] - mn);
                St[c][r] = p;
                sum += p;
            }
            sum += __shfl_xor_sync(0xFFFFFFFFu, sum, 1);
            sum += __shfl_xor_sync(0xFFFFFFFFu, sum, 2);
            if (part == 0) {
                float cr = __expf(mo - mn);
                l_s[r] = l_s[r] * cr + sum;
                m_s[r] = mn;
                corr_s[r] = cr;
            }
        }
        __syncthreads();

        #pragma unroll
        for (int i = 0; i < 4; i++) {
            float cr = corr_s[(ty << 2) + i];
            #pragma unroll
            for (int j = 0; j < 4; j++) acc[i][j] *= cr;
        }
        #pragma unroll 16
        for (int k = 0; k < 64; k++) {
            float4 a = *(const float4*)&St[k][ty << 2];
            float4 bb = *(const float4*)&Vs[k][tx << 2];
            float ar[4] = {a.x, a.y, a.z, a.w};
            float br[4] = {bb.x, bb.y, bb.z, bb.w};
            #pragma unroll
            for (int i = 0; i < 4; i++)
                #pragma unroll
                for (int j = 0; j < 4; j++)
                    acc[i][j] = fmaf(ar[i], br[j], acc[i][j]);
        }
        __syncthreads();
    }

    #pragma unroll
    for (int i = 0; i < 4; i++) {
        float inv = 1.0f / l_s[(ty << 2) + i];
        float4 o = make_float4(acc[i][0] * inv, acc[i][1] * inv,
                               acc[i][2] * inv, acc[i][3] * inv);
        *(float4*)&att[(size_t)(b * TT + q0 + (ty << 2) + i) * CC + h * HD + (tx << 2)] = o;
    }
}

// ---------------------------------------------------------------------------
extern "C" void kernel_launch(void* const* d_in, const int* in_sizes, int n_in,
                              void* d_out, int out_size)
{
    const float* x      = (const float*)d_in[0];
    const float* W_attn = (const float*)d_in[1];
    const float* W_proj = (const float*)d_in[2];
    float* out = (float*)d_out;

    void *qkv_p, *att_p, *xhi, *xlo, *wahi, *walo, *wphi, *wplo, *ahi, *alo;
    cudaGetSymbolAddress(&qkv_p, g_qkv);
    cudaGetSymbolAddress(&att_p, g_att);
    cudaGetSymbolAddress(&xhi, g_xhi);   cudaGetSymbolAddress(&xlo, g_xlo);
    cudaGetSymbolAddress(&wahi, g_wahi); cudaGetSymbolAddress(&walo, g_walo);
    cudaGetSymbolAddress(&wphi, g_wphi); cudaGetSymbolAddress(&wplo, g_wplo);
    cudaGetSymbolAddress(&ahi, g_ahi);   cudaGetSymbolAddress(&alo, g_alo);

    cudaFuncSetAttribute(flash_attn, cudaFuncAttributeMaxDynamicSharedMemorySize, SMEM_FLASH);
    cudaFuncSetAttribute(hgemm128, cudaFuncAttributeMaxDynamicSharedMemorySize, HG_SMEM);

    // Split fp32 inputs into (hi, lo) bf16 pairs
    split_hl<<<256, 256>>>(x, (__nv_bfloat16*)xhi, (__nv_bfloat16*)xlo, MM * CC);
    split_hl<<<256, 256>>>(W_attn, (__nv_bfloat16*)wahi, (__nv_bfloat16*)walo, C3 * CC);
    split_hl<<<256, 256>>>(W_proj, (__nv_bfloat16*)wphi, (__nv_bfloat16*)wplo, CC * CC);

    // 1) QKV projection (HMMA split-bf16): [4096,768] x [2304,768]^T
    hgemm128<<<dim3(C3 / 128, MM / 128), 256, HG_SMEM>>>(
        (const __nv_bfloat16*)xhi, (const __nv_bfloat16*)xlo,
        (const __nv_bfloat16*)wahi, (const __nv_bfloat16*)walo,
        (float*)qkv_p, C3, CC);

    // 2) Fused causal attention (fp32)
    flash_attn<<<dim3(TT / 64, NH, BB), 256, SMEM_FLASH>>>((const float*)qkv_p,
                                                           (float*)att_p);

    // 3) Split attention output, then output projection (HMMA)
    split_hl<<<256, 256>>>((const float*)att_p, (__nv_bfloat16*)ahi, (__nv_bfloat16*)alo, MM * CC);
    hgemm128<<<dim3(CC / 128, MM / 128), 256, HG_SMEM>>>(
        (const __nv_bfloat16*)ahi, (const __nv_bfloat16*)alo,
        (const __nv_bfloat16*)wphi, (const __nv_bfloat16*)wplo,
        out, CC, CC);
}

// round 14
// speedup vs baseline: 2.8867x; 1.9235x over previous
#include <cuda_runtime.h>
#include <cuda_bf16.h>
#include <cstdint>

// Problem constants
#define BB 2
#define TT 2048
#define CC 768
#define NH 12
#define HD 64
#define MM (BB*TT)        // 4096
#define C3 (3*CC)         // 2304

typedef unsigned int u32;

// ---------------- scratch (__device__ globals; no allocation) ---------------
__device__ __nv_bfloat16 g_xhi[(size_t)MM * CC],  g_xlo[(size_t)MM * CC];
__device__ __nv_bfloat16 g_wahi[(size_t)C3 * CC], g_walo[(size_t)C3 * CC];
__device__ __nv_bfloat16 g_wphi[(size_t)CC * CC], g_wplo[(size_t)CC * CC];
__device__ __nv_bfloat16 g_qkvh[(size_t)MM * C3], g_qkvl[(size_t)MM * C3];
__device__ __nv_bfloat16 g_athi[(size_t)MM * CC], g_atlo[(size_t)MM * CC];

extern __shared__ char dynsm[];

__device__ __forceinline__ u32 smem_u32(const void* p) {
    u32 a;
    asm("{ .reg .u64 t; cvta.to.shared.u64 t, %1; cvt.u32.u64 %0, t; }"
        : "=r"(a) : "l"(p));
    return a;
}

#define LDM_X4(r0, r1, r2, r3, addr)                                          \
    asm volatile("ldmatrix.sync.aligned.m8n8.x4.shared.b16 {%0,%1,%2,%3}, [%4];" \
        : "=r"(r0), "=r"(r1), "=r"(r2), "=r"(r3) : "r"(addr))

#define LDM_X4_T(r0, r1, r2, r3, addr)                                        \
    asm volatile("ldmatrix.sync.aligned.m8n8.x4.trans.shared.b16 {%0,%1,%2,%3}, [%4];" \
        : "=r"(r0), "=r"(r1), "=r"(r2), "=r"(r3) : "r"(addr))

#define MMA16816(d, a, b)                                                     \
    asm volatile("mma.sync.aligned.m16n8k16.row.col.f32.bf16.bf16.f32 "       \
        "{%0,%1,%2,%3}, {%4,%5,%6,%7}, {%8,%9}, {%0,%1,%2,%3};"               \
        : "+f"((d)[0]), "+f"((d)[1]), "+f"((d)[2]), "+f"((d)[3])              \
        : "r"((a)[0]), "r"((a)[1]), "r"((a)[2]), "r"((a)[3]),                 \
          "r"((b)[0]), "r"((b)[1]))

// pack two floats -> bf16x2 (low half = e0)
__device__ __forceinline__ u32 packbf2(float e0, float e1) {
    u32 d;
    asm("cvt.rn.bf16x2.f32 %0, %1, %2;" : "=r"(d) : "f"(e1), "f"(e0));
    return d;
}
__device__ __forceinline__ float bf16rt(float v) {   // round-trip through bf16
    return __bfloat162float(__float2bfloat16(v));
}

// ---------------------------------------------------------------------------
__global__ void split_hl(const float* __restrict__ in, __nv_bfloat16* __restrict__ hi,
                         __nv_bfloat16* __restrict__ lo, int n)
{
    int i = blockIdx.x * blockDim.x + threadIdx.x;
    int stride = gridDim.x * blockDim.x;
    for (; i < n; i += stride) {
        float v = in[i];
        __nv_bfloat16 h = __float2bfloat16(v);
        hi[i] = h;
        lo[i] = __float2bfloat16(v - __bfloat162float(h));
    }
}

// ---------------------------------------------------------------------------
// Split-bf16 HMMA GEMM (validated round 6). Epilogue writes either fp32 OR
// split hi/lo bf16 (outLo != nullptr).
// ---------------------------------------------------------------------------
#define PITCHB 144
#define TILE_B (128 * PITCHB)
#define HG_SMEM (4 * TILE_B)

__global__ void __launch_bounds__(256) hgemm128(
    const __nv_bfloat16* __restrict__ Ahi, const __nv_bfloat16* __restrict__ Alo,
    const __nv_bfloat16* __restrict__ Bhi, const __nv_bfloat16* __restrict__ Blo,
    float* __restrict__ outF, __nv_bfloat16* __restrict__ outHi,
    __nv_bfloat16* __restrict__ outLo, int Ndim, int Kdim)
{
    char* smem = dynsm;
    const u32 sb = smem_u32(smem);
    const int tid = threadIdx.x;
    const int lane = tid & 31;
    const int wid = tid >> 5;
    const int wm = (wid & 1) * 64;
    const int wn = (wid >> 1) * 32;
    const int m0 = blockIdx.y * 128, n0 = blockIdx.x * 128;

    const u32 SA_HI = 0, SA_LO = TILE_B, SB_HI = 2 * TILE_B, SB_LO = 3 * TILE_B;

    const __nv_bfloat16* srcs[4] = {
        Ahi + (size_t)m0 * Kdim, Alo + (size_t)m0 * Kdim,
        Bhi + (size_t)n0 * Kdim, Blo + (size_t)n0 * Kdim };
    const u32 dsts[4] = { SA_HI, SA_LO, SB_HI, SB_LO };

    const u32 a_row_off = (u32)(wm + (lane & 15)) * PITCHB;
    const u32 a_col_off = (u32)((lane >> 4) << 3) * 2;
    const u32 b_row_off = (u32)(wn + (lane & 7) + ((lane >> 4) << 3)) * PITCHB;
    const u32 b_col_off = (u32)(((lane >> 3) & 1) << 3) * 2;

    float acc[4][4][4] = {};
    const int nChunks = Kdim >> 6;

    for (int kt = 0; kt < nChunks; kt++) {
        __syncthreads();
        #pragma unroll
        for (int t = 0; t < 4; t++) {
            const __nv_bfloat16* base = srcs[t] + kt * 64;
            #pragma unroll
            for (int i = 0; i < 4; i++) {
                int idx = i * 256 + tid;
                int r = idx >> 3, s = idx & 7;
                uint4 v = *(const uint4*)(base + (size_t)r * Kdim + s * 8);
                *(uint4*)(smem + dsts[t] + r * PITCHB + s * 16) = v;
            }
        }
        __syncthreads();

        #pragma unroll
        for (int kf = 0; kf < 64; kf += 16) {
            const u32 kbyte = (u32)kf * 2;
            u32 ah[4][4], bcur[4][2], aother[4][4];

            #pragma unroll
            for (int fi = 0; fi < 4; fi++) {
                u32 ad = sb + SA_HI + a_row_off + fi * (16 * PITCHB) + kbyte + a_col_off;
                LDM_X4(ah[fi][0], ah[fi][1], ah[fi][2], ah[fi][3], ad);
            }
            #pragma unroll
            for (int p = 0; p < 2; p++) {
                u32 bd = sb + SB_HI + b_row_off + p * (16 * PITCHB) + kbyte + b_col_off;
                LDM_X4(bcur[2*p][0], bcur[2*p][1], bcur[2*p+1][0], bcur[2*p+1][1], bd);
            }
            #pragma unroll
            for (int fi = 0; fi < 4; fi++)
                #pragma unroll
                for (int fj = 0; fj < 4; fj++)
                    MMA16816(acc[fi][fj], ah[fi], bcur[fj]);

            #pragma unroll
            for (int fi = 0; fi < 4; fi++) {
                u32 ad = sb + SA_LO + a_row_off + fi * (16 * PITCHB) + kbyte + a_col_off;
                LDM_X4(aother[fi][0], aother[fi][1], aother[fi][2], aother[fi][3], ad);
            }
            #pragma unroll
            for (int fi = 0; fi < 4; fi++)
                #pragma unroll
                for (int fj = 0; fj < 4; fj++)
                    MMA16816(acc[fi][fj], aother[fi], bcur[fj]);

            #pragma unroll
            for (int p = 0; p < 2; p++) {
                u32 bd = sb + SB_LO + b_row_off + p * (16 * PITCHB) + kbyte + b_col_off;
                LDM_X4(bcur[2*p][0], bcur[2*p][1], bcur[2*p+1][0], bcur[2*p+1][1], bd);
            }
            #pragma unroll
            for (int fi = 0; fi < 4; fi++)
                #pragma unroll
                for (int fj = 0; fj < 4; fj++)
                    MMA16816(acc[fi][fj], ah[fi], bcur[fj]);
        }
    }

    const int rbase = m0 + wm + (lane >> 2);
    const int cbase = n0 + wn + 2 * (lane & 3);
    if (outLo) {
        #pragma unroll
        for (int fi = 0; fi < 4; fi++)
            #pragma unroll
            for (int fj = 0; fj < 4; fj++) {
                size_t p0 = (size_t)(rbase + 16 * fi) * Ndim + cbase + 8 * fj;
                size_t p1 = (size_t)(rbase + 16 * fi + 8) * Ndim + cbase + 8 * fj;
                float a0 = acc[fi][fj][0], a1 = acc[fi][fj][1];
                float a2 = acc[fi][fj][2], a3 = acc[fi][fj][3];
                *(u32*)(outHi + p0) = packbf2(a0, a1);
                *(u32*)(outLo + p0) = packbf2(a0 - bf16rt(a0), a1 - bf16rt(a1));
                *(u32*)(outHi + p1) = packbf2(a2, a3);
                *(u32*)(outLo + p1) = packbf2(a2 - bf16rt(a2), a3 - bf16rt(a3));
            }
    } else {
        #pragma unroll
        for (int fi = 0; fi < 4; fi++)
            #pragma unroll
            for (int fj = 0; fj < 4; fj++) {
                float* o0 = outF + (size_t)(rbase + 16 * fi) * Ndim + cbase + 8 * fj;
                float* o1 = outF + (size_t)(rbase + 16 * fi + 8) * Ndim + cbase + 8 * fj;
                *(float2*)o0 = make_float2(acc[fi][fj][0], acc[fi][fj][1]);
                *(float2*)o1 = make_float2(acc[fi][fj][2], acc[fi][fj][3]);
            }
    }
}

// ---------------------------------------------------------------------------
// HMMA flash attention (split-bf16, FA2 layout).
// Grid (T/128, H, B), 256 threads = 8 warps x 16 q-rows. KV tiles of 64.
// ---------------------------------------------------------------------------
#define FPITCH 144                       // 72 bf16 per smem row
#define SMEM_FA 36864                    // max(Q stage 2x128x144, KV 4x64x144)

__global__ void __launch_bounds__(256) flash_hmma(
    const __nv_bfloat16* __restrict__ qh, const __nv_bfloat16* __restrict__ ql,
    __nv_bfloat16* __restrict__ oh, __nv_bfloat16* __restrict__ ol)
{
    char* smem = dynsm;
    const u32 sb = smem_u32(smem);
    const int tid = threadIdx.x;
    const int lane = tid & 31;
    const int wid = tid >> 5;
    const int qi = blockIdx.x, h = blockIdx.y, b = blockIdx.z;
    const int q0 = qi * 128;
    const int c2 = (lane & 3) << 1;      // col pair offset within n8 frag
    const int rL = lane >> 2;            // row within 8-row group

    // ---- stage Q (hi at 0, lo at 18432), extract A-frags ----
    #pragma unroll
    for (int i = 0; i < 4; i++) {
        int idx = i * 256 + tid;         // 0..1023
        int r = idx >> 3, s = idx & 7;
        size_t src = (size_t)(b * TT + q0 + r) * C3 + h * HD + s * 8;
        *(uint4*)(smem + r * FPITCH + s * 16) = *(const uint4*)(qh + src);
        *(uint4*)(smem + 18432 + r * FPITCH + s * 16) = *(const uint4*)(ql + src);
    }
    __syncthreads();

    u32 qfh[4][4], qfl[4][4];
    {
        const u32 arow = (u32)(wid * 16 + (lane & 15)) * FPITCH;
        const u32 acol = (u32)((lane >> 4) << 3) * 2;
        #pragma unroll
        for (int kk = 0; kk < 4; kk++) {
            u32 ad = sb + arow + kk * 32 + acol;
            LDM_X4(qfh[kk][0], qfh[kk][1], qfh[kk][2], qfh[kk][3], ad);
            LDM_X4(qfl[kk][0], qfl[kk][1], qfl[kk][2], qfl[kk][3], ad + 18432);
        }
    }

    float accO[8][4] = {};
    float m0r = -1e30f, m1r = -1e30f, l0r = 0.0f, l1r = 0.0f;

    const u32 KHI = 0, KLO = 9216, VHI = 18432, VLO = 27648;
    // B-frag (non-trans, for K): per n-quarter p
    const u32 b_row = (u32)((lane & 7) + ((lane >> 4) << 3)) * FPITCH;
    const u32 b_col = (u32)(((lane >> 3) & 1) << 3) * 2;
    // B-frag (trans, for V): per kstep kk / d-quarter p
    const u32 v_row = (u32)((lane & 7) + (((lane >> 3) & 1) << 3)) * FPITCH;
    const u32 v_col = (u32)((lane >> 4) << 3) * 2;

    const int ktEnd = 2 * qi + 2;
    for (int kt = 0; kt < ktEnd; kt++) {
        const int kb = kt * 64;
        __syncthreads();
        // load K/V hi/lo tiles (64 x 64 bf16 each)
        #pragma unroll
        for (int t = 0; t < 4; t++) {
            const __nv_bfloat16* srcb = (t & 1) ? ql : qh;
            const int colofs = ((t < 2) ? CC : 2 * CC) + h * HD;
            const u32 dst = (t < 2) ? ((t & 1) ? KLO : KHI) : ((t & 1) ? VLO : VHI);
            #pragma unroll
            for (int i = 0; i < 2; i++) {
                int idx = i * 256 + tid;     // 0..511
                int r = idx >> 3, s = idx & 7;
                uint4 v = *(const uint4*)(srcb + (size_t)(b * TT + kb + r) * C3 + colofs + s * 8);
                *(uint4*)(smem + dst + r * FPITCH + s * 16) = v;
            }
        }
        __syncthreads();

        // ---- S = Q K^T (3-pass split) ----
        float s[8][4] = {};
        #pragma unroll
        for (int kk = 0; kk < 4; kk++) {
            const u32 kbyte = (u32)kk * 32;
            u32 bh[8][2], bl[8][2];
            #pragma unroll
            for (int p = 0; p < 4; p++) {
                u32 bd = sb + KHI + b_row + p * (16 * FPITCH) + kbyte + b_col;
                LDM_X4(bh[2*p][0], bh[2*p][1], bh[2*p+1][0], bh[2*p+1][1], bd);
            }
            #pragma unroll
            for (int j = 0; j < 8; j++) MMA16816(s[j], qfh[kk], bh[j]);
            #pragma unroll
            for (int p = 0; p < 4; p++) {
                u32 bd = sb + KLO + b_row + p * (16 * FPITCH) + kbyte + b_col;
                LDM_X4(bl[2*p][0], bl[2*p][1], bl[2*p+1][0], bl[2*p+1][1], bd);
            }
            #pragma unroll
            for (int j = 0; j < 8; j++) {
                MMA16816(s[j], qfh[kk], bl[j]);
                MMA16816(s[j], qfl[kk], bh[j]);
            }
        }

        // ---- scale + causal mask ----
        const int r0g = q0 + wid * 16 + rL;   // global row for regs 0,1
        #pragma unroll
        for (int j = 0; j < 8; j++) {
            s[j][0] *= 0.125f; s[j][1] *= 0.125f;
            s[j][2] *= 0.125f; s[j][3] *= 0.125f;
        }
        if (kb + 63 > q0 + wid * 16) {
            #pragma unroll
            for (int j = 0; j < 8; j++) {
                int col = kb + 8 * j + c2;
                if (col > r0g)     s[j][0] = -1e30f;
                if (col + 1 > r0g) s[j][1] = -1e30f;
                if (col > r0g + 8)     s[j][2] = -1e30f;
                if (col + 1 > r0g + 8) s[j][3] = -1e30f;
            }
        }

        // ---- online softmax (two rows per lane, 4-lane shfl reduce) ----
        float mx0 = -1e30f, mx1 = -1e30f;
        #pragma unroll
        for (int j = 0; j < 8; j++) {
            mx0 = fmaxf(mx0, fmaxf(s[j][0], s[j][1]));
            mx1 = fmaxf(mx1, fmaxf(s[j][2], s[j][3]));
        }
        mx0 = fmaxf(mx0, __shfl_xor_sync(0xFFFFFFFFu, mx0, 1));
        mx0 = fmaxf(mx0, __shfl_xor_sync(0xFFFFFFFFu, mx0, 2));
        mx1 = fmaxf(mx1, __shfl_xor_sync(0xFFFFFFFFu, mx1, 1));
        mx1 = fmaxf(mx1, __shfl_xor_sync(0xFFFFFFFFu, mx1, 2));
        float mn0 = fmaxf(m0r, mx0), mn1 = fmaxf(m1r, mx1);
        float sum0 = 0.0f, sum1 = 0.0f;
        #pragma unroll
        for (int j = 0; j < 8; j++) {
            s[j][0] = __expf(s[j][0] - mn0); sum0 += s[j][0];
            s[j][1] = __expf(s[j][1] - mn0); sum0 += s[j][1];
            s[j][2] = __expf(s[j][2] - mn1); sum1 += s[j][2];
            s[j][3] = __expf(s[j][3] - mn1); sum1 += s[j][3];
        }
        sum0 += __shfl_xor_sync(0xFFFFFFFFu, sum0, 1);
        sum0 += __shfl_xor_sync(0xFFFFFFFFu, sum0, 2);
        sum1 += __shfl_xor_sync(0xFFFFFFFFu, sum1, 1);
        sum1 += __shfl_xor_sync(0xFFFFFFFFu, sum1, 2);
        float cr0 = __expf(m0r - mn0), cr1 = __expf(m1r - mn1);
        l0r = l0r * cr0 + sum0; m0r = mn0;
        l1r = l1r * cr1 + sum1; m1r = mn1;
        #pragma unroll
        for (int j = 0; j < 8; j++) {
            accO[j][0] *= cr0; accO[j][1] *= cr0;
            accO[j][2] *= cr1; accO[j][3] *= cr1;
        }

        // ---- build P A-frags (hi/lo) in registers ----
        u32 pfh[4][4], pfl[4][4];
        #pragma unroll
        for (int kk = 0; kk < 4; kk++) {
            float e[8] = { s[2*kk][0], s[2*kk][1], s[2*kk][2], s[2*kk][3],
                           s[2*kk+1][0], s[2*kk+1][1], s[2*kk+1][2], s[2*kk+1][3] };
            #pragma unroll
            for (int q = 0; q < 4; q++) {
                float e0 = e[2*q], e1 = e[2*q+1];
                pfh[kk][q] = packbf2(e0, e1);
                pfl[kk][q] = packbf2(e0 - bf16rt(e0), e1 - bf16rt(e1));
            }
        }

        // ---- O += P V (3-pass split, V via ldmatrix.trans) ----
        #pragma unroll
        for (int kk = 0; kk < 4; kk++) {
            const u32 krow = (u32)(kk * 16) * FPITCH;
            u32 vh[8][2], vl[8][2];
            #pragma unroll
            for (int p = 0; p < 4; p++) {
                u32 vd = sb + VHI + krow + v_row + (u32)(p * 16) * 2 + v_col;
                LDM_X4_T(vh[2*p][0], vh[2*p][1], vh[2*p+1][0], vh[2*p+1][1], vd);
            }
            #pragma unroll
            for (int j = 0; j < 8; j++) MMA16816(accO[j], pfh[kk], vh[j]);
            #pragma unroll
            for (int p = 0; p < 4; p++) {
                u32 vd = sb + VLO + krow + v_row + (u32)(p * 16) * 2 + v_col;
                LDM_X4_T(vl[2*p][0], vl[2*p][1], vl[2*p+1][0], vl[2*p+1][1], vd);
            }
            #pragma unroll
            for (int j = 0; j < 8; j++) {
                MMA16816(accO[j], pfh[kk], vl[j]);
                MMA16816(accO[j], pfl[kk], vh[j]);
            }
        }
    }

    // ---- epilogue: normalize, write hi/lo bf16 ----
    const float inv0 = 1.0f / l0r, inv1 = 1.0f / l1r;
    const size_t row0 = (size_t)(b * TT + q0 + wid * 16 + rL) * CC;
    const size_t row1 = row0 + (size_t)8 * CC;
    const int colb = h * HD + c2;
    #pragma unroll
    for (int j = 0; j < 8; j++) {
        float o00 = accO[j][0] * inv0, o01 = accO[j][1] * inv0;
        float o10 = accO[j][2] * inv1, o11 = accO[j][3] * inv1;
        int col = colb + 8 * j;
        *(u32*)(oh + row0 + col) = packbf2(o00, o01);
        *(u32*)(ol + row0 + col) = packbf2(o00 - bf16rt(o00), o01 - bf16rt(o01));
        *(u32*)(oh + row1 + col) = packbf2(o10, o11);
        *(u32*)(ol + row1 + col) = packbf2(o10 - bf16rt(o10), o11 - bf16rt(o11));
    }
}

// ---------------------------------------------------------------------------
extern "C" void kernel_launch(void* const* d_in, const int* in_sizes, int n_in,
                              void* d_out, int out_size)
{
    const float* x      = (const float*)d_in[0];
    const float* W_attn = (const float*)d_in[1];
    const float* W_proj = (const float*)d_in[2];
    float* out = (float*)d_out;

    void *xhi, *xlo, *wahi, *walo, *wphi, *wplo, *qh, *qlp, *ath, *atl;
    cudaGetSymbolAddress(&xhi, g_xhi);   cudaGetSymbolAddress(&xlo, g_xlo);
    cudaGetSymbolAddress(&wahi, g_wahi); cudaGetSymbolAddress(&walo, g_walo);
    cudaGetSymbolAddress(&wphi, g_wphi); cudaGetSymbolAddress(&wplo, g_wplo);
    cudaGetSymbolAddress(&qh, g_qkvh);   cudaGetSymbolAddress(&qlp, g_qkvl);
    cudaGetSymbolAddress(&ath, g_athi);  cudaGetSymbolAddress(&atl, g_atlo);

    cudaFuncSetAttribute(hgemm128, cudaFuncAttributeMaxDynamicSharedMemorySize, HG_SMEM);
    cudaFuncSetAttribute(flash_hmma, cudaFuncAttributeMaxDynamicSharedMemorySize, SMEM_FA);

    split_hl<<<256, 256>>>(x, (__nv_bfloat16*)xhi, (__nv_bfloat16*)xlo, MM * CC);
    split_hl<<<256, 256>>>(W_attn, (__nv_bfloat16*)wahi, (__nv_bfloat16*)walo, C3 * CC);
    split_hl<<<256, 256>>>(W_proj, (__nv_bfloat16*)wphi, (__nv_bfloat16*)wplo, CC * CC);

    // 1) QKV projection -> split bf16 output
    hgemm128<<<dim3(C3 / 128, MM / 128), 256, HG_SMEM>>>(
        (const __nv_bfloat16*)xhi, (const __nv_bfloat16*)xlo,
        (const __nv_bfloat16*)wahi, (const __nv_bfloat16*)walo,
        nullptr, (__nv_bfloat16*)qh, (__nv_bfloat16*)qlp, C3, CC);

    // 2) HMMA flash attention -> split bf16 output
    flash_hmma<<<dim3(TT / 128, NH, BB), 256, SMEM_FA>>>(
        (const __nv_bfloat16*)qh, (const __nv_bfloat16*)qlp,
        (__nv_bfloat16*)ath, (__nv_bfloat16*)atl);

    // 3) Output projection -> fp32 out
    hgemm128<<<dim3(CC / 128, MM / 128), 256, HG_SMEM>>>(
        (const __nv_bfloat16*)ath, (const __nv_bfloat16*)atl,
        (const __nv_bfloat16*)wphi, (const __nv_bfloat16*)wplo,
        out, nullptr, nullptr, CC, CC);
}

// round 15
// speedup vs baseline: 3.1618x; 1.0953x over previous
#include <cuda_runtime.h>
#include <cuda_bf16.h>
#include <cstdint>

// Problem constants
#define BB 2
#define TT 2048
#define CC 768
#define NH 12
#define HD 64
#define MM (BB*TT)        // 4096
#define C3 (3*CC)         // 2304

typedef unsigned int u32;

// ---------------- scratch (__device__ globals; no allocation) ---------------
__device__ __nv_bfloat16 g_xhi[(size_t)MM * CC],  g_xlo[(size_t)MM * CC];
__device__ __nv_bfloat16 g_wahi[(size_t)C3 * CC], g_walo[(size_t)C3 * CC];
__device__ __nv_bfloat16 g_wphi[(size_t)CC * CC], g_wplo[(size_t)CC * CC];
__device__ __nv_bfloat16 g_qkvh[(size_t)MM * C3], g_qkvl[(size_t)MM * C3];
__device__ __nv_bfloat16 g_athi[(size_t)MM * CC], g_atlo[(size_t)MM * CC];

extern __shared__ char dynsm[];

__device__ __forceinline__ u32 smem_u32(const void* p) {
    u32 a;
    asm("{ .reg .u64 t; cvta.to.shared.u64 t, %1; cvt.u32.u64 %0, t; }"
        : "=r"(a) : "l"(p));
    return a;
}

#define LDM_X4(r0, r1, r2, r3, addr)                                          \
    asm volatile("ldmatrix.sync.aligned.m8n8.x4.shared.b16 {%0,%1,%2,%3}, [%4];" \
        : "=r"(r0), "=r"(r1), "=r"(r2), "=r"(r3) : "r"(addr))

#define LDM_X4_T(r0, r1, r2, r3, addr)                                        \
    asm volatile("ldmatrix.sync.aligned.m8n8.x4.trans.shared.b16 {%0,%1,%2,%3}, [%4];" \
        : "=r"(r0), "=r"(r1), "=r"(r2), "=r"(r3) : "r"(addr))

#define MMA16816(d, a, b)                                                     \
    asm volatile("mma.sync.aligned.m16n8k16.row.col.f32.bf16.bf16.f32 "       \
        "{%0,%1,%2,%3}, {%4,%5,%6,%7}, {%8,%9}, {%0,%1,%2,%3};"               \
        : "+f"((d)[0]), "+f"((d)[1]), "+f"((d)[2]), "+f"((d)[3])              \
        : "r"((a)[0]), "r"((a)[1]), "r"((a)[2]), "r"((a)[3]),                 \
          "r"((b)[0]), "r"((b)[1]))

// cp.async (sm_80 baseline; available at compute_103)
#define CP16(dst, src)                                                        \
    asm volatile("cp.async.cg.shared.global [%0], [%1], 16;"                  \
                 :: "r"(dst), "l"(src))
#define CP_COMMIT() asm volatile("cp.async.commit_group;" ::: "memory")
#define CP_WAIT1()  asm volatile("cp.async.wait_group 1;" ::: "memory")
#define CP_WAIT0()  asm volatile("cp.async.wait_group 0;" ::: "memory")

// pack two floats -> bf16x2 (low half = e0)
__device__ __forceinline__ u32 packbf2(float e0, float e1) {
    u32 d;
    asm("cvt.rn.bf16x2.f32 %0, %1, %2;" : "=r"(d) : "f"(e1), "f"(e0));
    return d;
}
__device__ __forceinline__ float bf16rt(float v) {   // round-trip through bf16
    return __bfloat162float(__float2bfloat16(v));
}

// ---------------------------------------------------------------------------
__global__ void split_hl(const float* __restrict__ in, __nv_bfloat16* __restrict__ hi,
                         __nv_bfloat16* __restrict__ lo, int n)
{
    int i = blockIdx.x * blockDim.x + threadIdx.x;
    int stride = gridDim.x * blockDim.x;
    for (; i < n; i += stride) {
        float v = in[i];
        __nv_bfloat16 h = __float2bfloat16(v);
        hi[i] = h;
        lo[i] = __float2bfloat16(v - __bfloat162float(h));
    }
}

// ---------------------------------------------------------------------------
// Split-bf16 HMMA GEMM, cp.async double-buffered K-chunks.
// ---------------------------------------------------------------------------
#define PITCHB 144
#define TILE_B (128 * PITCHB)
#define BUF_B  (4 * TILE_B)              // 73728 per buffer
#define HG_SMEM (2 * BUF_B)              // 147456

__global__ void __launch_bounds__(256) hgemm128(
    const __nv_bfloat16* __restrict__ Ahi, const __nv_bfloat16* __restrict__ Alo,
    const __nv_bfloat16* __restrict__ Bhi, const __nv_bfloat16* __restrict__ Blo,
    float* __restrict__ outF, __nv_bfloat16* __restrict__ outHi,
    __nv_bfloat16* __restrict__ outLo, int Ndim, int Kdim)
{
    char* smem = dynsm;
    const u32 sb = smem_u32(smem);
    const int tid = threadIdx.x;
    const int lane = tid & 31;
    const int wid = tid >> 5;
    const int wm = (wid & 1) * 64;
    const int wn = (wid >> 1) * 32;
    const int m0 = blockIdx.y * 128, n0 = blockIdx.x * 128;

    const u32 SA_HI = 0, SA_LO = TILE_B, SB_HI = 2 * TILE_B, SB_LO = 3 * TILE_B;

    const __nv_bfloat16* srcs[4] = {
        Ahi + (size_t)m0 * Kdim, Alo + (size_t)m0 * Kdim,
        Bhi + (size_t)n0 * Kdim, Blo + (size_t)n0 * Kdim };
    const u32 dsts[4] = { SA_HI, SA_LO, SB_HI, SB_LO };

    const u32 a_row_off = (u32)(wm + (lane & 15)) * PITCHB;
    const u32 a_col_off = (u32)((lane >> 4) << 3) * 2;
    const u32 b_row_off = (u32)(wn + (lane & 7) + ((lane >> 4) << 3)) * PITCHB;
    const u32 b_col_off = (u32)(((lane >> 3) & 1) << 3) * 2;

    float acc[4][4][4] = {};
    const int nChunks = Kdim >> 6;

    // async chunk loader: 16 cp.async x 16B per thread
    auto load_chunk = [&](int kt, int buf) {
        const u32 bofs = (u32)buf * BUF_B;
        #pragma unroll
        for (int t = 0; t < 4; t++) {
            const __nv_bfloat16* base = srcs[t] + kt * 64;
            #pragma unroll
            for (int i = 0; i < 4; i++) {
                int idx = i * 256 + tid;
                int r = idx >> 3, s = idx & 7;
                CP16(sb + bofs + dsts[t] + (u32)(r * PITCHB + s * 16),
                     base + (size_t)r * Kdim + s * 8);
            }
        }
    };

    load_chunk(0, 0);
    CP_COMMIT();

    for (int kt = 0; kt < nChunks; kt++) {
        const int cur = kt & 1;
        const bool more = (kt + 1) < nChunks;
        if (more) { load_chunk(kt + 1, cur ^ 1); CP_COMMIT(); CP_WAIT1(); }
        else      { CP_WAIT0(); }
        __syncthreads();

        const u32 bufb = sb + (u32)cur * BUF_B;
        #pragma unroll
        for (int kf = 0; kf < 64; kf += 16) {
            const u32 kbyte = (u32)kf * 2;
            u32 ah[4][4], bcur[4][2], aother[4][4];

            #pragma unroll
            for (int fi = 0; fi < 4; fi++) {
                u32 ad = bufb + SA_HI + a_row_off + fi * (16 * PITCHB) + kbyte + a_col_off;
                LDM_X4(ah[fi][0], ah[fi][1], ah[fi][2], ah[fi][3], ad);
            }
            #pragma unroll
            for (int p = 0; p < 2; p++) {
                u32 bd = bufb + SB_HI + b_row_off + p * (16 * PITCHB) + kbyte + b_col_off;
                LDM_X4(bcur[2*p][0], bcur[2*p][1], bcur[2*p+1][0], bcur[2*p+1][1], bd);
            }
            #pragma unroll
            for (int fi = 0; fi < 4; fi++)
                #pragma unroll
                for (int fj = 0; fj < 4; fj++)
                    MMA16816(acc[fi][fj], ah[fi], bcur[fj]);

            #pragma unroll
            for (int fi = 0; fi < 4; fi++) {
                u32 ad = bufb + SA_LO + a_row_off + fi * (16 * PITCHB) + kbyte + a_col_off;
                LDM_X4(aother[fi][0], aother[fi][1], aother[fi][2], aother[fi][3], ad);
            }
            #pragma unroll
            for (int fi = 0; fi < 4; fi++)
                #pragma unroll
                for (int fj = 0; fj < 4; fj++)
                    MMA16816(acc[fi][fj], aother[fi], bcur[fj]);

            #pragma unroll
            for (int p = 0; p < 2; p++) {
                u32 bd = bufb + SB_LO + b_row_off + p * (16 * PITCHB) + kbyte + b_col_off;
                LDM_X4(bcur[2*p][0], bcur[2*p][1], bcur[2*p+1][0], bcur[2*p+1][1], bd);
            }
            #pragma unroll
            for (int fi = 0; fi < 4; fi++)
                #pragma unroll
                for (int fj = 0; fj < 4; fj++)
                    MMA16816(acc[fi][fj], ah[fi], bcur[fj]);
        }
        __syncthreads();   // done reading buf[cur] before it is overwritten
    }

    const int rbase = m0 + wm + (lane >> 2);
    const int cbase = n0 + wn + 2 * (lane & 3);
    if (outLo) {
        #pragma unroll
        for (int fi = 0; fi < 4; fi++)
            #pragma unroll
            for (int fj = 0; fj < 4; fj++) {
                size_t p0 = (size_t)(rbase + 16 * fi) * Ndim + cbase + 8 * fj;
                size_t p1 = (size_t)(rbase + 16 * fi + 8) * Ndim + cbase + 8 * fj;
                float a0 = acc[fi][fj][0], a1 = acc[fi][fj][1];
                float a2 = acc[fi][fj][2], a3 = acc[fi][fj][3];
                *(u32*)(outHi + p0) = packbf2(a0, a1);
                *(u32*)(outLo + p0) = packbf2(a0 - bf16rt(a0), a1 - bf16rt(a1));
                *(u32*)(outHi + p1) = packbf2(a2, a3);
                *(u32*)(outLo + p1) = packbf2(a2 - bf16rt(a2), a3 - bf16rt(a3));
            }
    } else {
        #pragma unroll
        for (int fi = 0; fi < 4; fi++)
            #pragma unroll
            for (int fj = 0; fj < 4; fj++) {
                float* o0 = outF + (size_t)(rbase + 16 * fi) * Ndim + cbase + 8 * fj;
                float* o1 = outF + (size_t)(rbase + 16 * fi + 8) * Ndim + cbase + 8 * fj;
                *(float2*)o0 = make_float2(acc[fi][fj][0], acc[fi][fj][1]);
                *(float2*)o1 = make_float2(acc[fi][fj][2], acc[fi][fj][3]);
            }
    }
}

// ---------------------------------------------------------------------------
// HMMA flash attention, cp.async double-buffered KV tiles.
// Grid (T/128, H, B), 256 threads = 8 warps x 16 q-rows. KV tiles of 64.
// ---------------------------------------------------------------------------
#define FPITCH 144                       // 72 bf16 per smem row
#define KVBUF 36864                      // 4 tiles x 64 x 144
#define SMEM_FA (2 * KVBUF)              // 73728

__global__ void __launch_bounds__(256) flash_hmma(
    const __nv_bfloat16* __restrict__ qh, const __nv_bfloat16* __restrict__ ql,
    __nv_bfloat16* __restrict__ oh, __nv_bfloat16* __restrict__ ol)
{
    char* smem = dynsm;
    const u32 sb = smem_u32(smem);
    const int tid = threadIdx.x;
    const int lane = tid & 31;
    const int wid = tid >> 5;
    const int qi = blockIdx.x, h = blockIdx.y, b = blockIdx.z;
    const int q0 = qi * 128;
    const int c2 = (lane & 3) << 1;      // col pair offset within n8 frag
    const int rL = lane >> 2;            // row within 8-row group

    // ---- stage Q (hi at 0, lo at 18432) in buf0 region, extract A-frags ----
    #pragma unroll
    for (int i = 0; i < 4; i++) {
        int idx = i * 256 + tid;         // 0..1023
        int r = idx >> 3, s = idx & 7;
        size_t src = (size_t)(b * TT + q0 + r) * C3 + h * HD + s * 8;
        *(uint4*)(smem + r * FPITCH + s * 16) = *(const uint4*)(qh + src);
        *(uint4*)(smem + 18432 + r * FPITCH + s * 16) = *(const uint4*)(ql + src);
    }
    __syncthreads();

    u32 qfh[4][4], qfl[4][4];
    {
        const u32 arow = (u32)(wid * 16 + (lane & 15)) * FPITCH;
        const u32 acol = (u32)((lane >> 4) << 3) * 2;
        #pragma unroll
        for (int kk = 0; kk < 4; kk++) {
            u32 ad = sb + arow + kk * 32 + acol;
            LDM_X4(qfh[kk][0], qfh[kk][1], qfh[kk][2], qfh[kk][3], ad);
            LDM_X4(qfl[kk][0], qfl[kk][1], qfl[kk][2], qfl[kk][3], ad + 18432);
        }
    }
    __syncthreads();   // all warps done reading Q staging before KV overwrites buf0

    float accO[8][4] = {};
    float m0r = -1e30f, m1r = -1e30f, l0r = 0.0f, l1r = 0.0f;

    const u32 KHI = 0, KLO = 9216, VHI = 18432, VLO = 27648;
    const u32 b_row = (u32)((lane & 7) + ((lane >> 4) << 3)) * FPITCH;
    const u32 b_col = (u32)(((lane >> 3) & 1) << 3) * 2;
    const u32 v_row = (u32)((lane & 7) + (((lane >> 3) & 1) << 3)) * FPITCH;
    const u32 v_col = (u32)((lane >> 4) << 3) * 2;

    // async KV tile loader: 8 cp.async x 16B per thread
    auto load_kv = [&](int kt, int buf) {
        const u32 bofs = (u32)buf * KVBUF;
        const int kb = kt * 64;
        #pragma unroll
        for (int t = 0; t < 4; t++) {
            const __nv_bfloat16* srcb = (t & 1) ? ql : qh;
            const int colofs = ((t < 2) ? CC : 2 * CC) + h * HD;
            const u32 dst = bofs + ((t < 2) ? ((t & 1) ? KLO : KHI)
                                            : ((t & 1) ? VLO : VHI));
            #pragma unroll
            for (int i = 0; i < 2; i++) {
                int idx = i * 256 + tid;     // 0..511
                int r = idx >> 3, s = idx & 7;
                CP16(sb + dst + (u32)(r * FPITCH + s * 16),
                     srcb + (size_t)(b * TT + kb + r) * C3 + colofs + s * 8);
            }
        }
    };

    const int ktEnd = 2 * qi + 2;
    load_kv(0, 0);
    CP_COMMIT();

    for (int kt = 0; kt < ktEnd; kt++) {
        const int cur = kt & 1;
        const int kb = kt * 64;
        const bool more = (kt + 1) < ktEnd;
        if (more) { load_kv(kt + 1, cur ^ 1); CP_COMMIT(); CP_WAIT1(); }
        else      { CP_WAIT0(); }
        __syncthreads();

        const u32 bufb = sb + (u32)cur * KVBUF;

        // ---- S = Q K^T (3-pass split) ----
        float s[8][4] = {};
        #pragma unroll
        for (int kk = 0; kk < 4; kk++) {
            const u32 kbyte = (u32)kk * 32;
            u32 bh[8][2], bl[8][2];
            #pragma unroll
            for (int p = 0; p < 4; p++) {
                u32 bd = bufb + KHI + b_row + p * (16 * FPITCH) + kbyte + b_col;
                LDM_X4(bh[2*p][0], bh[2*p][1], bh[2*p+1][0], bh[2*p+1][1], bd);
            }
            #pragma unroll
            for (int j = 0; j < 8; j++) MMA16816(s[j], qfh[kk], bh[j]);
            #pragma unroll
            for (int p = 0; p < 4; p++) {
                u32 bd = bufb + KLO + b_row + p * (16 * FPITCH) + kbyte + b_col;
                LDM_X4(bl[2*p][0], bl[2*p][1], bl[2*p+1][0], bl[2*p+1][1], bd);
            }
            #pragma unroll
            for (int j = 0; j < 8; j++) {
                MMA16816(s[j], qfh[kk], bl[j]);
                MMA16816(s[j], qfl[kk], bh[j]);
            }
        }

        // ---- scale + causal mask ----
        const int r0g = q0 + wid * 16 + rL;
        #pragma unroll
        for (int j = 0; j < 8; j++) {
            s[j][0] *= 0.125f; s[j][1] *= 0.125f;
            s[j][2] *= 0.125f; s[j][3] *= 0.125f;
        }
        if (kb + 63 > q0 + wid * 16) {
            #pragma unroll
            for (int j = 0; j < 8; j++) {
                int col = kb + 8 * j + c2;
                if (col > r0g)     s[j][0] = -1e30f;
                if (col + 1 > r0g) s[j][1] = -1e30f;
                if (col > r0g + 8)     s[j][2] = -1e30f;
                if (col + 1 > r0g + 8) s[j][3] = -1e30f;
            }
        }

        // ---- online softmax (two rows per lane, 4-lane shfl reduce) ----
        float mx0 = -1e30f, mx1 = -1e30f;
        #pragma unroll
        for (int j = 0; j < 8; j++) {
            mx0 = fmaxf(mx0, fmaxf(s[j][0], s[j][1]));
            mx1 = fmaxf(mx1, fmaxf(s[j][2], s[j][3]));
        }
        mx0 = fmaxf(mx0, __shfl_xor_sync(0xFFFFFFFFu, mx0, 1));
        mx0 = fmaxf(mx0, __shfl_xor_sync(0xFFFFFFFFu, mx0, 2));
        mx1 = fmaxf(mx1, __shfl_xor_sync(0xFFFFFFFFu, mx1, 1));
        mx1 = fmaxf(mx1, __shfl_xor_sync(0xFFFFFFFFu, mx1, 2));
        float mn0 = fmaxf(m0r, mx0), mn1 = fmaxf(m1r, mx1);
        float sum0 = 0.0f, sum1 = 0.0f;
        #pragma unroll
        for (int j = 0; j < 8; j++) {
            s[j][0] = __expf(s[j][0] - mn0); sum0 += s[j][0];
            s[j][1] = __expf(s[j][1] - mn0); sum0 += s[j][1];
            s[j][2] = __expf(s[j][2] - mn1); sum1 += s[j][2];
            s[j][3] = __expf(s[j][3] - mn1); sum1 += s[j][3];
        }
        sum0 += __shfl_xor_sync(0xFFFFFFFFu, sum0, 1);
        sum0 += __shfl_xor_sync(0xFFFFFFFFu, sum0, 2);
        sum1 += __shfl_xor_sync(0xFFFFFFFFu, sum1, 1);
        sum1 += __shfl_xor_sync(0xFFFFFFFFu, sum1, 2);
        float cr0 = __expf(m0r - mn0), cr1 = __expf(m1r - mn1);
        l0r = l0r * cr0 + sum0; m0r = mn0;
        l1r = l1r * cr1 + sum1; m1r = mn1;
        #pragma unroll
        for (int j = 0; j < 8; j++) {
            accO[j][0] *= cr0; accO[j][1] *= cr0;
            accO[j][2] *= cr1; accO[j][3] *= cr1;
        }

        // ---- build P A-frags (hi/lo) in registers ----
        u32 pfh[4][4], pfl[4][4];
        #pragma unroll
        for (int kk = 0; kk < 4; kk++) {
            float e[8] = { s[2*kk][0], s[2*kk][1], s[2*kk][2], s[2*kk][3],
                           s[2*kk+1][0], s[2*kk+1][1], s[2*kk+1][2], s[2*kk+1][3] };
            #pragma unroll
            for (int q = 0; q < 4; q++) {
                float e0 = e[2*q], e1 = e[2*q+1];
                pfh[kk][q] = packbf2(e0, e1);
                pfl[kk][q] = packbf2(e0 - bf16rt(e0), e1 - bf16rt(e1));
            }
        }

        // ---- O += P V (3-pass split, V via ldmatrix.trans) ----
        #pragma unroll
        for (int kk = 0; kk < 4; kk++) {
            const u32 krow = (u32)(kk * 16) * FPITCH;
            u32 vh[8][2], vl[8][2];
            #pragma unroll
            for (int p = 0; p < 4; p++) {
                u32 vd = bufb + VHI + krow + v_row + (u32)(p * 16) * 2 + v_col;
                LDM_X4_T(vh[2*p][0], vh[2*p][1], vh[2*p+1][0], vh[2*p+1][1], vd);
            }
            #pragma unroll
            for (int j = 0; j < 8; j++) MMA16816(accO[j], pfh[kk], vh[j]);
            #pragma unroll
            for (int p = 0; p < 4; p++) {
                u32 vd = bufb + VLO + krow + v_row + (u32)(p * 16) * 2 + v_col;
                LDM_X4_T(vl[2*p][0], vl[2*p][1], vl[2*p+1][0], vl[2*p+1][1], vd);
            }
            #pragma unroll
            for (int j = 0; j < 8; j++) {
                MMA16816(accO[j], pfh[kk], vl[j]);
                MMA16816(accO[j], pfl[kk], vh[j]);
            }
        }
        __syncthreads();   // done reading buf[cur] before it is overwritten
    }

    // ---- epilogue: normalize, write hi/lo bf16 ----
    const float inv0 = 1.0f / l0r, inv1 = 1.0f / l1r;
    const size_t row0 = (size_t)(b * TT + q0 + wid * 16 + rL) * CC;
    const size_t row1 = row0 + (size_t)8 * CC;
    const int colb = h * HD + c2;
    #pragma unroll
    for (int j = 0; j < 8; j++) {
        float o00 = accO[j][0] * inv0, o01 = accO[j][1] * inv0;
        float o10 = accO[j][2] * inv1, o11 = accO[j][3] * inv1;
        int col = colb + 8 * j;
        *(u32*)(oh + row0 + col) = packbf2(o00, o01);
        *(u32*)(ol + row0 + col) = packbf2(o00 - bf16rt(o00), o01 - bf16rt(o01));
        *(u32*)(oh + row1 + col) = packbf2(o10, o11);
        *(u32*)(ol + row1 + col) = packbf2(o10 - bf16rt(o10), o11 - bf16rt(o11));
    }
}

// ---------------------------------------------------------------------------
extern "C" void kernel_launch(void* const* d_in, const int* in_sizes, int n_in,
                              void* d_out, int out_size)
{
    const float* x      = (const float*)d_in[0];
    const float* W_attn = (const float*)d_in[1];
    const float* W_proj = (const float*)d_in[2];
    float* out = (float*)d_out;

    void *xhi, *xlo, *wahi, *walo, *wphi, *wplo, *qh, *qlp, *ath, *atl;
    cudaGetSymbolAddress(&xhi, g_xhi);   cudaGetSymbolAddress(&xlo, g_xlo);
    cudaGetSymbolAddress(&wahi, g_wahi); cudaGetSymbolAddress(&walo, g_walo);
    cudaGetSymbolAddress(&wphi, g_wphi); cudaGetSymbolAddress(&wplo, g_wplo);
    cudaGetSymbolAddress(&qh, g_qkvh);   cudaGetSymbolAddress(&qlp, g_qkvl);
    cudaGetSymbolAddress(&ath, g_athi);  cudaGetSymbolAddress(&atl, g_atlo);

    cudaFuncSetAttribute(hgemm128, cudaFuncAttributeMaxDynamicSharedMemorySize, HG_SMEM);
    cudaFuncSetAttribute(flash_hmma, cudaFuncAttributeMaxDynamicSharedMemorySize, SMEM_FA);

    split_hl<<<1024, 256>>>(x, (__nv_bfloat16*)xhi, (__nv_bfloat16*)xlo, MM * CC);
    split_hl<<<1024, 256>>>(W_attn, (__nv_bfloat16*)wahi, (__nv_bfloat16*)walo, C3 * CC);
    split_hl<<<1024, 256>>>(W_proj, (__nv_bfloat16*)wphi, (__nv_bfloat16*)wplo, CC * CC);

    // 1) QKV projection -> split bf16 output
    hgemm128<<<dim3(C3 / 128, MM / 128), 256, HG_SMEM>>>(
        (const __nv_bfloat16*)xhi, (const __nv_bfloat16*)xlo,
        (const __nv_bfloat16*)wahi, (const __nv_bfloat16*)walo,
        nullptr, (__nv_bfloat16*)qh, (__nv_bfloat16*)qlp, C3, CC);

    // 2) HMMA flash attention -> split bf16 output
    flash_hmma<<<dim3(TT / 128, NH, BB), 256, SMEM_FA>>>(
        (const __nv_bfloat16*)qh, (const __nv_bfloat16*)qlp,
        (__nv_bfloat16*)ath, (__nv_bfloat16*)atl);

    // 3) Output projection -> fp32 out
    hgemm128<<<dim3(CC / 128, MM / 128), 256, HG_SMEM>>>(
        (const __nv_bfloat16*)ath, (const __nv_bfloat16*)atl,
        (const __nv_bfloat16*)wphi, (const __nv_bfloat16*)wplo,
        out, nullptr, nullptr, CC, CC);
}